// round 1
// baseline (speedup 1.0000x reference)
#include <cuda_runtime.h>

// Steerable encoder: RBF feature map via separable-Gaussian rank decomposition.
//
//  out0[k][j] = sum_i ex_ij * ey_ik
//  out1[k][j] = (sum_i ex_ij * ey_ik * Y_i0) / out0
//  out2[k][j] = (sum_i ex_ij * ey_ik * Y_i1) / out0
//  ex_ij = exp(-0.5 (x_j - X_i.x)^2),  ey_ik = exp(-0.5 (y_k - X_i.y)^2)
//
// x_j = -2 + j*(4/127),  y_k = +2 - k*(4/127)   (y counted backwards)

#define N_AXIS   128
#define NPIX     (N_AXIS * N_AXIS)          // 16384
#define NPTS     8192
#define NSLICE   16                         // split-i factor
#define KT       8                          // k-rows per CTA
#define CI       128                        // i-chunk size
#define I_PER_SLICE (NPTS / NSLICE)         // 512

// partial sums: [slice][channel][k][j]
__device__ float g_partial[NSLICE * 3 * NPIX];

__global__ __launch_bounds__(128, 2)
void se_accum_kernel(const float* __restrict__ X, const float* __restrict__ Y)
{
    __shared__ float sh_a[CI][24];   // [i][k*3+c], row = 96B (16B aligned)
    __shared__ float sh_x[CI];

    const int j     = threadIdx.x;         // output column (x index)
    const int slice = blockIdx.x;          // i-slice
    const int k0    = blockIdx.y * KT;     // first k-row of tile

    const float step = 4.0f / 127.0f;
    const float xj = -2.0f + (float)j * step;

    float yk[KT];
    #pragma unroll
    for (int k = 0; k < KT; k++) yk[k] = 2.0f - (float)(k0 + k) * step;

    float acc[24];
    #pragma unroll
    for (int t = 0; t < 24; t++) acc[t] = 0.0f;

    const int i0 = slice * I_PER_SLICE;

    for (int chunk = 0; chunk < I_PER_SLICE / CI; chunk++) {
        // ---- cooperative fill: thread j handles point i = ibase + j ----
        {
            const int i = i0 + chunk * CI + j;
            float2 xp = ((const float2*)X)[i];
            float2 yp = ((const float2*)Y)[i];
            sh_x[j] = xp.x;
            const float py = xp.y;
            #pragma unroll
            for (int k = 0; k < KT; k++) {
                float dy = yk[k] - py;
                float e  = __expf(-0.5f * dy * dy);
                sh_a[j][k * 3 + 0] = e;
                sh_a[j][k * 3 + 1] = e * yp.x;
                sh_a[j][k * 3 + 2] = e * yp.y;
            }
        }
        __syncthreads();

        // ---- main accumulation: 1 exp + 6 LDS.128 (broadcast) + 24 FFMA / i ----
        #pragma unroll 4
        for (int ii = 0; ii < CI; ii++) {
            float dx = xj - sh_x[ii];
            float e  = __expf(-0.5f * dx * dx);
            #pragma unroll
            for (int m = 0; m < 6; m++) {
                float4 v = *(const float4*)&sh_a[ii][m * 4];
                acc[m * 4 + 0] += e * v.x;
                acc[m * 4 + 1] += e * v.y;
                acc[m * 4 + 2] += e * v.z;
                acc[m * 4 + 3] += e * v.w;
            }
        }
        __syncthreads();
    }

    // ---- write partial sums (coalesced in j) ----
    float* p = g_partial + slice * (3 * NPIX);
    #pragma unroll
    for (int idx = 0; idx < 24; idx++) {
        int k = idx / 3, c = idx % 3;
        p[c * NPIX + (k0 + k) * N_AXIS + j] = acc[idx];
    }
}

__global__ void se_reduce_kernel(float* __restrict__ out)
{
    const int p = blockIdx.x * blockDim.x + threadIdx.x;   // pixel 0..16383
    float s0 = 0.0f, s1 = 0.0f, s2 = 0.0f;
    #pragma unroll
    for (int s = 0; s < NSLICE; s++) {
        const float* base = g_partial + s * (3 * NPIX);
        s0 += base[p];
        s1 += base[NPIX + p];
        s2 += base[2 * NPIX + p];
    }
    out[p]            = s0;
    out[NPIX + p]     = s1 / s0;
    out[2 * NPIX + p] = s2 / s0;
}

extern "C" void kernel_launch(void* const* d_in, const int* in_sizes, int n_in,
                              void* d_out, int out_size)
{
    const float* X = (const float*)d_in[0];
    const float* Y = (const float*)d_in[1];
    float* out = (float*)d_out;

    dim3 grid(NSLICE, N_AXIS / KT);   // 16 x 16 = 256 CTAs
    se_accum_kernel<<<grid, 128>>>(X, Y);
    se_reduce_kernel<<<NPIX / 256, 256>>>(out);
}

// round 2
// speedup vs baseline: 1.2671x; 1.2671x over previous
#include <cuda_runtime.h>

// Steerable encoder: separable RBF, packed-f32x2 FMA accumulation.
//
//  out0[k][j] = sum_i ex_ij * ey_ik
//  out1[k][j] = (sum_i ex_ij * ey_ik * Y_i0) / out0
//  out2[k][j] = (sum_i ex_ij * ey_ik * Y_i1) / out0

#define N_AXIS   128
#define NPIX     (N_AXIS * N_AXIS)     // 16384
#define NPTS     8192
#define NSLICE   37                    // 8 ktiles * 37 slices = 296 CTAs = 2/SM
#define KT       16                    // k-rows per CTA
#define CI       128                   // i-chunk size

// partial sums: [slice][channel][k][j]
__device__ float g_partial[NSLICE * 3 * NPIX];

__device__ __forceinline__ unsigned long long ffma2(unsigned long long a,
                                                    unsigned long long b,
                                                    unsigned long long c)
{
    unsigned long long d;
    asm("fma.rn.f32x2 %0, %1, %2, %3;" : "=l"(d) : "l"(a), "l"(b), "l"(c));
    return d;
}

__global__ __launch_bounds__(128, 2)
void se_accum_kernel(const float* __restrict__ X, const float* __restrict__ Y)
{
    __shared__ float sh_a[CI][48];   // [i][k*3+c], row = 192B (16B aligned)
    __shared__ float sh_x[CI];

    const int j     = threadIdx.x;         // output column (x index)
    const int slice = blockIdx.x;          // i-slice (0..36)
    const int k0    = blockIdx.y * KT;     // first k-row of tile

    const float step = 4.0f / 127.0f;
    const float xj = -2.0f + (float)j * step;

    float yk[KT];
    #pragma unroll
    for (int k = 0; k < KT; k++) yk[k] = 2.0f - (float)(k0 + k) * step;

    unsigned long long acc[24];            // 48 packed f32 accumulators
    #pragma unroll
    for (int t = 0; t < 24; t++) acc[t] = 0ULL;

    const int lo = (NPTS * slice) / NSLICE;
    const int hi = (NPTS * (slice + 1)) / NSLICE;

    for (int base = lo; base < hi; base += CI) {
        const int cnt = min(CI, hi - base);

        // ---- cooperative fill: thread j handles point i = base + j ----
        if (j < cnt) {
            const int i = base + j;
            float2 xp = ((const float2*)X)[i];
            float2 yp = ((const float2*)Y)[i];
            sh_x[j] = xp.x;
            const float py = xp.y;
            #pragma unroll
            for (int k = 0; k < KT; k++) {
                float dy = yk[k] - py;
                float e  = __expf(-0.5f * dy * dy);
                sh_a[j][k * 3 + 0] = e;
                sh_a[j][k * 3 + 1] = e * yp.x;
                sh_a[j][k * 3 + 2] = e * yp.y;
            }
        }
        __syncthreads();

        // ---- main loop: 1 exp + 12 LDS.128 (broadcast) + 24 FFMA2 / i ----
        #pragma unroll 4
        for (int ii = 0; ii < cnt; ii++) {
            float dx = xj - sh_x[ii];
            float ef = __expf(-0.5f * dx * dx);
            unsigned int eb = __float_as_uint(ef);
            unsigned long long e2;
            asm("mov.b64 %0, {%1, %1};" : "=l"(e2) : "r"(eb));

            const ulonglong2* row = (const ulonglong2*)sh_a[ii];
            #pragma unroll
            for (int u = 0; u < 12; u++) {
                ulonglong2 v = row[u];
                acc[2 * u + 0] = ffma2(e2, v.x, acc[2 * u + 0]);
                acc[2 * u + 1] = ffma2(e2, v.y, acc[2 * u + 1]);
            }
        }
        __syncthreads();
    }

    // ---- unpack + write partial sums (coalesced in j) ----
    float res[48];
    #pragma unroll
    for (int u = 0; u < 24; u++) {
        res[2 * u + 0] = __uint_as_float((unsigned int)(acc[u] & 0xffffffffULL));
        res[2 * u + 1] = __uint_as_float((unsigned int)(acc[u] >> 32));
    }

    float* p = g_partial + slice * (3 * NPIX);
    #pragma unroll
    for (int t = 0; t < 48; t++) {
        int k = t / 3, c = t % 3;
        p[c * NPIX + (k0 + k) * N_AXIS + j] = res[t];
    }
}

__global__ __launch_bounds__(128)
void se_reduce_kernel(float* __restrict__ out)
{
    const int p = blockIdx.x * blockDim.x + threadIdx.x;   // pixel 0..16383
    float s0 = 0.0f, s1 = 0.0f, s2 = 0.0f;
    #pragma unroll
    for (int s = 0; s < NSLICE; s++) {
        const float* base = g_partial + s * (3 * NPIX);
        s0 += base[p];
        s1 += base[NPIX + p];
        s2 += base[2 * NPIX + p];
    }
    float r = 1.0f / s0;
    out[p]            = s0;
    out[NPIX + p]     = s1 * r;
    out[2 * NPIX + p] = s2 * r;
}

extern "C" void kernel_launch(void* const* d_in, const int* in_sizes, int n_in,
                              void* d_out, int out_size)
{
    const float* X = (const float*)d_in[0];
    const float* Y = (const float*)d_in[1];
    float* out = (float*)d_out;

    dim3 grid(NSLICE, N_AXIS / KT);   // 37 x 8 = 296 CTAs = exactly 2 per SM
    se_accum_kernel<<<grid, 128>>>(X, Y);
    se_reduce_kernel<<<NPIX / 128, 128>>>(out);
}